// round 8
// baseline (speedup 1.0000x reference)
#include <cuda_runtime.h>

#define N_CLASSES 128

// Global scratch (no allocations allowed). Zeroed at module load; the
// last-done block resets everything, so graph replays are deterministic.
__device__ float    g_sum[N_CLASSES];
__device__ float    g_cnt[N_CLASSES];
__device__ unsigned g_ticket;

// Integer warp reductions (sm_103a: s32/u32 only)
__device__ __forceinline__ int redux_add_s32(int v) {
    int r;
    asm volatile("redux.sync.add.s32 %0, %1, 0xffffffff;" : "=r"(r) : "r"(v));
    return r;
}
__device__ __forceinline__ unsigned redux_max_u32(unsigned v) {
    unsigned r;
    asm volatile("redux.sync.max.u32 %0, %1, 0xffffffff;" : "=r"(r) : "r"(v));
    return r;
}
__device__ __forceinline__ unsigned redux_min_u32(unsigned v) {
    unsigned r;
    asm volatile("redux.sync.min.u32 %0, %1, 0xffffffff;" : "=r"(r) : "r"(v));
    return r;
}

// Fixed-point scales (worst-case |sum| < 2^31 with >= 2x margin)
#define SE_SCALE  1048576.0f      // 2^20
#define SY_SCALE  8388608.0f      // 2^23
#define SYH_SCALE 2097152.0f      // 2^21

__device__ __forceinline__ float4 ldcs4(const float4* p) {
    return __ldcs(p);             // evict-first streaming load
}

__device__ __forceinline__ void process_row(const float4& h, const float4& yv,
                                            int lane,
                                            float* s_sum, float* s_cnt)
{
    float se  = __expf(h.x) + __expf(h.y) + __expf(h.z) + __expf(h.w);
    float sy  = yv.x + yv.y + yv.z + yv.w;
    float syh = yv.x * h.x;
    syh = fmaf(yv.y, h.y, syh);
    syh = fmaf(yv.z, h.z, syh);
    syh = fmaf(yv.w, h.w, syh);

    int ise  = redux_add_s32(__float2int_rn(se  * SE_SCALE));
    int isy  = redux_add_s32(__float2int_rn(sy  * SY_SCALE));
    int isyh = redux_add_s32(__float2int_rn(syh * SYH_SCALE));

    // argmax of y, first-max semantics (y >= 0: u32 bits order-isomorphic)
    float amv = yv.x; unsigned ami = lane * 4u;
    if (yv.y > amv) { amv = yv.y; ami = lane * 4u + 1u; }
    if (yv.z > amv) { amv = yv.z; ami = lane * 4u + 2u; }
    if (yv.w > amv) { amv = yv.w; ami = lane * 4u + 3u; }

    unsigned mybits  = __float_as_uint(amv);
    unsigned maxbits = redux_max_u32(mybits);
    unsigned cand    = (mybits == maxbits) ? ami : 0xffffffffu;
    unsigned cls     = redux_min_u32(cand);

    if (lane == 0) {
        float fse  = (float)ise  * (1.0f / SE_SCALE);
        float fsy  = (float)isy  * (1.0f / SY_SCALE);
        float fsyh = (float)isyh * (1.0f / SYH_SCALE);
        float loss = fsy * __logf(fse) - fsyh;
        atomicAdd(&s_sum[cls], loss);
        atomicAdd(&s_cnt[cls], 1.0f);
    }
}

__global__ void __launch_bounds__(256, 4)
class_loss_kernel(const float* __restrict__ y_hat,
                  const float* __restrict__ y,
                  float* __restrict__ out,
                  int B)
{
    __shared__ float s_sum[N_CLASSES];
    __shared__ float s_cnt[N_CLASSES];
    __shared__ bool  s_last;

    const int tid  = threadIdx.x;
    const int lane = tid & 31;
    const int warp = tid >> 5;

    if (tid < N_CLASSES) { s_sum[tid] = 0.0f; s_cnt[tid] = 0.0f; }
    __syncthreads();

    const int totWarps = gridDim.x * (blockDim.x >> 5);
    const int w        = blockIdx.x * (blockDim.x >> 5) + warp;
    const int stride   = totWarps * 2;           // rows per warp-iteration x warps
    const int Beven    = B & ~1;                 // steady loop covers even prefix

    const float4* __restrict__ yh4 = (const float4*)y_hat;
    const float4* __restrict__ yy4 = (const float4*)y;

    // ---- software pipeline: loads for iteration n+1 issued BEFORE the
    //      compute tail of iteration n, so 8 LDG.128 are outstanding
    //      during every reduction tail (keeps HBM request stream full) ----
    int r = w * 2;
    if (r + 1 < Beven) {
        int b0 = r * 32 + lane;
        float4 h0 = ldcs4(yh4 + b0);
        float4 h1 = ldcs4(yh4 + b0 + 32);
        float4 y0 = ldcs4(yy4 + b0);
        float4 y1 = ldcs4(yy4 + b0 + 32);

        for (;;) {
            const int rn   = r + stride;
            const bool more = (rn + 1 < Beven);

            float4 nh0, nh1, ny0, ny1;
            if (more) {
                const int bn = rn * 32 + lane;
                nh0 = ldcs4(yh4 + bn);
                nh1 = ldcs4(yh4 + bn + 32);
                ny0 = ldcs4(yy4 + bn);
                ny1 = ldcs4(yy4 + bn + 32);
            }

            process_row(h0, y0, lane, s_sum, s_cnt);
            process_row(h1, y1, lane, s_sum, s_cnt);

            if (!more) break;
            h0 = nh0; h1 = nh1; y0 = ny0; y1 = ny1;
            r = rn;
        }
    }

    // odd-B remainder: at most one row, handled by warp 0
    if ((B & 1) && w == 0) {
        const int b = (B - 1) * 32 + lane;
        const float4 h  = ldcs4(yh4 + b);
        const float4 yv = ldcs4(yy4 + b);
        process_row(h, yv, lane, s_sum, s_cnt);
    }

    __syncthreads();
    if (tid < N_CLASSES) {
        atomicAdd(&g_sum[tid], s_sum[tid]);
        atomicAdd(&g_cnt[tid], s_cnt[tid]);
    }

    // ---- last-block-done finalize ----
    __threadfence();
    if (tid == 0) {
        unsigned t = atomicAdd(&g_ticket, 1u);
        s_last = (t == gridDim.x - 1);
    }
    __syncthreads();

    if (s_last && tid < N_CLASSES) {
        float s = __ldcg(&g_sum[tid]);
        float c = __ldcg(&g_cnt[tid]);
        out[tid] = (c > 0.0f) ? (s / c) : 0.0f;
        g_sum[tid] = 0.0f;
        g_cnt[tid] = 0.0f;
        if (tid == 0) g_ticket = 0u;
    }
}

extern "C" void kernel_launch(void* const* d_in, const int* in_sizes, int n_in,
                              void* d_out, int out_size)
{
    const float* y_hat = (const float*)d_in[0];
    const float* y     = (const float*)d_in[1];
    float* out = (float*)d_out;

    const int B = in_sizes[0] / N_CLASSES;   // 500000

    const int threads = 256;                 // 8 warps/block
    int blocks = 148 * 8;
    const int rows_per_iter = (threads / 32) * 2;
    int needed = (B + rows_per_iter - 1) / rows_per_iter;
    if (blocks > needed) blocks = needed;

    class_loss_kernel<<<blocks, threads>>>(y_hat, y, out, B);
}

// round 9
// speedup vs baseline: 1.1516x; 1.1516x over previous
#include <cuda_runtime.h>

#define N_CLASSES 128

// Global scratch (no allocations allowed). Zeroed at module load; the
// last-done block resets everything, so graph replays are deterministic.
__device__ float    g_sum[N_CLASSES];
__device__ float    g_cnt[N_CLASSES];
__device__ unsigned g_ticket;

// Integer warp reductions (sm_103a: s32/u32 only)
__device__ __forceinline__ int redux_add_s32(int v) {
    int r;
    asm volatile("redux.sync.add.s32 %0, %1, 0xffffffff;" : "=r"(r) : "r"(v));
    return r;
}
__device__ __forceinline__ unsigned redux_max_u32(unsigned v) {
    unsigned r;
    asm volatile("redux.sync.max.u32 %0, %1, 0xffffffff;" : "=r"(r) : "r"(v));
    return r;
}
__device__ __forceinline__ unsigned redux_min_u32(unsigned v) {
    unsigned r;
    asm volatile("redux.sync.min.u32 %0, %1, 0xffffffff;" : "=r"(r) : "r"(v));
    return r;
}

// Fixed-point scales (worst-case |sum| < 2^31 with >= 2x margin)
#define SE_SCALE  1048576.0f      // 2^20
#define SY_SCALE  8388608.0f      // 2^23
#define SYH_SCALE 2097152.0f      // 2^21

__device__ __forceinline__ float4 ldcs4(const float4* p) {
    return __ldcs(p);             // evict-first streaming load
}

__device__ __forceinline__ void process_row(const float4& h, const float4& yv,
                                            int lane,
                                            float* s_sum, float* s_cnt)
{
    float se  = __expf(h.x) + __expf(h.y) + __expf(h.z) + __expf(h.w);
    float sy  = yv.x + yv.y + yv.z + yv.w;
    float syh = yv.x * h.x;
    syh = fmaf(yv.y, h.y, syh);
    syh = fmaf(yv.z, h.z, syh);
    syh = fmaf(yv.w, h.w, syh);

    int ise  = redux_add_s32(__float2int_rn(se  * SE_SCALE));
    int isy  = redux_add_s32(__float2int_rn(sy  * SY_SCALE));
    int isyh = redux_add_s32(__float2int_rn(syh * SYH_SCALE));

    // argmax of y, first-max semantics (y >= 0: u32 bits order-isomorphic)
    float amv = yv.x; unsigned ami = lane * 4u;
    if (yv.y > amv) { amv = yv.y; ami = lane * 4u + 1u; }
    if (yv.z > amv) { amv = yv.z; ami = lane * 4u + 2u; }
    if (yv.w > amv) { amv = yv.w; ami = lane * 4u + 3u; }

    unsigned mybits  = __float_as_uint(amv);
    unsigned maxbits = redux_max_u32(mybits);
    unsigned cand    = (mybits == maxbits) ? ami : 0xffffffffu;
    unsigned cls     = redux_min_u32(cand);

    if (lane == 0) {
        float fse  = (float)ise  * (1.0f / SE_SCALE);
        float fsy  = (float)isy  * (1.0f / SY_SCALE);
        float fsyh = (float)isyh * (1.0f / SYH_SCALE);
        float loss = fsy * __logf(fse) - fsyh;
        atomicAdd(&s_sum[cls], loss);
        atomicAdd(&s_cnt[cls], 1.0f);
    }
}

__global__ void __launch_bounds__(256, 3)
class_loss_kernel(const float* __restrict__ y_hat,
                  const float* __restrict__ y,
                  float* __restrict__ out,
                  int B)
{
    __shared__ float s_sum[N_CLASSES];
    __shared__ float s_cnt[N_CLASSES];
    __shared__ bool  s_last;

    const int tid  = threadIdx.x;
    const int lane = tid & 31;
    const int warp = tid >> 5;

    if (tid < N_CLASSES) { s_sum[tid] = 0.0f; s_cnt[tid] = 0.0f; }
    __syncthreads();

    const int totWarps = gridDim.x * (blockDim.x >> 5);
    const int w        = blockIdx.x * (blockDim.x >> 5) + warp;

    const float4* __restrict__ yh4 = (const float4*)y_hat;
    const float4* __restrict__ yy4 = (const float4*)y;

    // 6 rows per warp-iteration: 12 independent LDG.128 front-batched by
    // ptxas (flat straight-line block — proven pattern from R7, scaled up).
    int r0 = w * 6;
    const int stride = totWarps * 6;
    for (; r0 + 5 < B; r0 += stride) {
        const int b0 = (r0    ) * 32 + lane;
        const int b1 = (r0 + 1) * 32 + lane;
        const int b2 = (r0 + 2) * 32 + lane;
        const int b3 = (r0 + 3) * 32 + lane;
        const int b4 = (r0 + 4) * 32 + lane;
        const int b5 = (r0 + 5) * 32 + lane;

        const float4 h0 = ldcs4(yh4 + b0);
        const float4 h1 = ldcs4(yh4 + b1);
        const float4 h2 = ldcs4(yh4 + b2);
        const float4 h3 = ldcs4(yh4 + b3);
        const float4 h4 = ldcs4(yh4 + b4);
        const float4 h5 = ldcs4(yh4 + b5);
        const float4 y0 = ldcs4(yy4 + b0);
        const float4 y1 = ldcs4(yy4 + b1);
        const float4 y2 = ldcs4(yy4 + b2);
        const float4 y3 = ldcs4(yy4 + b3);
        const float4 y4 = ldcs4(yy4 + b4);
        const float4 y5 = ldcs4(yy4 + b5);

        process_row(h0, y0, lane, s_sum, s_cnt);
        process_row(h1, y1, lane, s_sum, s_cnt);
        process_row(h2, y2, lane, s_sum, s_cnt);
        process_row(h3, y3, lane, s_sum, s_cnt);
        process_row(h4, y4, lane, s_sum, s_cnt);
        process_row(h5, y5, lane, s_sum, s_cnt);
    }
    // tail (< 6 rows for this warp)
    for (; r0 < B; r0++) {
        const int b = r0 * 32 + lane;
        const float4 h  = ldcs4(yh4 + b);
        const float4 yv = ldcs4(yy4 + b);
        process_row(h, yv, lane, s_sum, s_cnt);
    }

    __syncthreads();
    if (tid < N_CLASSES) {
        atomicAdd(&g_sum[tid], s_sum[tid]);
        atomicAdd(&g_cnt[tid], s_cnt[tid]);
    }

    // ---- last-block-done finalize ----
    __threadfence();
    if (tid == 0) {
        unsigned t = atomicAdd(&g_ticket, 1u);
        s_last = (t == gridDim.x - 1);
    }
    __syncthreads();

    if (s_last && tid < N_CLASSES) {
        float s = __ldcg(&g_sum[tid]);
        float c = __ldcg(&g_cnt[tid]);
        out[tid] = (c > 0.0f) ? (s / c) : 0.0f;
        g_sum[tid] = 0.0f;
        g_cnt[tid] = 0.0f;
        if (tid == 0) g_ticket = 0u;
    }
}

extern "C" void kernel_launch(void* const* d_in, const int* in_sizes, int n_in,
                              void* d_out, int out_size)
{
    const float* y_hat = (const float*)d_in[0];
    const float* y     = (const float*)d_in[1];
    float* out = (float*)d_out;

    const int B = in_sizes[0] / N_CLASSES;   // 500000

    const int threads = 256;                 // 8 warps/block
    int blocks = 148 * 3;                    // exactly one wave at occ 3
    const int rows_per_iter = (threads / 32) * 6;   // 48 rows/block/iter
    int needed = (B + rows_per_iter - 1) / rows_per_iter;
    if (blocks > needed) blocks = needed;

    class_loss_kernel<<<blocks, threads>>>(y_hat, y, out, B);
}